// round 12
// baseline (speedup 1.0000x reference)
#include <cuda_runtime.h>
#include <cuda_fp16.h>
#include <cstdint>

#define T_TOK 4096
#define D_IN  2048
#define D_MOE 768
#define TWO_DM 1536

// ---- tiling: 256M x 128N per CTA, 512 threads, 1 CTA/SM ----
#define BM 256
#define BK 64                        // halves per K chunk = 128B swizzled row
#define A_BYTES  (BM * 128)          // 32 KB
#define B_BYTES  (128 * 128)         // 16 KB
#define STAGE_BYTES (A_BYTES + B_BYTES)   // 48 KB
#define S_STAGES 3
#define SMEM_TOTAL (S_STAGES * STAGE_BYTES)   // 144 KB

#define G1_TILES (16 * 12)           // bm 0..15 x bn 0..11 (h cols 64/tile), bm-major
#define G2_TILES (16 * 16)           // bm 0..15 x bn 0..15 (out cols 128/tile)
#define N_TILES  (G1_TILES + G2_TILES)

// Scratch (device globals: allocation-free per harness rules)
__device__ __align__(16) __half g_xh[T_TOK * D_IN];
__device__ __align__(16) __half g_guw[TWO_DM * D_IN];
__device__ __align__(16) __half g_dw[D_IN * D_MOE];
__device__ __align__(16) __half g_h[T_TOK * D_MOE];
__device__ unsigned int g_tile_ctr;
__device__ unsigned int g_ready[16];   // per 256-row block: finished G1 tiles (of 12)

// ---------------------------------------------------------------------------
// PTX helpers (non-'a' features only: cp.async, ldmatrix, mma.sync)
// ---------------------------------------------------------------------------
__device__ __forceinline__ uint32_t smem_u32(const void* p) {
    uint32_t a;
    asm("{ .reg .u64 t; cvta.to.shared.u64 t, %1; cvt.u32.u64 %0, t; }" : "=r"(a) : "l"(p));
    return a;
}
__device__ __forceinline__ void cp16(uint32_t saddr, const void* gaddr) {
    asm volatile("cp.async.cg.shared.global [%0], [%1], 16;" :: "r"(saddr), "l"(gaddr));
}
#define CP_COMMIT() asm volatile("cp.async.commit_group;" ::: "memory")
#define CP_WAIT(n)  asm volatile("cp.async.wait_group %0;" :: "n"(n) : "memory")

__device__ __forceinline__ void ldsm_x4(uint32_t& r0, uint32_t& r1, uint32_t& r2, uint32_t& r3,
                                        uint32_t addr) {
    asm volatile("ldmatrix.sync.aligned.m8n8.x4.shared.b16 {%0,%1,%2,%3}, [%4];"
                 : "=r"(r0), "=r"(r1), "=r"(r2), "=r"(r3) : "r"(addr));
}
__device__ __forceinline__ void mma_16816(float* c, const uint32_t* a, const uint32_t* b) {
    asm volatile(
        "mma.sync.aligned.m16n8k16.row.col.f32.f16.f16.f32 "
        "{%0,%1,%2,%3}, {%4,%5,%6,%7}, {%8,%9}, {%0,%1,%2,%3};"
        : "+f"(c[0]), "+f"(c[1]), "+f"(c[2]), "+f"(c[3])
        : "r"(a[0]), "r"(a[1]), "r"(a[2]), "r"(a[3]), "r"(b[0]), "r"(b[1]));
}
__device__ __forceinline__ void st_cs_f2(float* p, float a, float b) {
    asm volatile("st.global.cs.v2.f32 [%0], {%1, %2};" :: "l"(p), "f"(a), "f"(b) : "memory");
}
__device__ __forceinline__ float silu_f(float v) { return v / (1.0f + __expf(-v)); }

// ---------------------------------------------------------------------------
// fp32 -> fp16 conversion + work-queue reset. expert_idx read on device.
// ---------------------------------------------------------------------------
__global__ void convert_kernel(const float* __restrict__ x,
                               const float* __restrict__ gup,
                               const float* __restrict__ dp,
                               const int* __restrict__ eidx) {
    if (blockIdx.x == 0 && threadIdx.x < 17) {
        if (threadIdx.x == 16) g_tile_ctr = 0;
        else g_ready[threadIdx.x] = 0;
    }
    const int e = *eidx;
    const float4* gu4 = (const float4*)(gup + (size_t)e * TWO_DM * D_IN);
    const float4* dw4 = (const float4*)(dp + (size_t)e * D_IN * D_MOE);
    const float4* x4 = (const float4*)x;
    uint4* xo = (uint4*)g_xh;
    uint4* go = (uint4*)g_guw;
    uint4* do_ = (uint4*)g_dw;
    const int stride = gridDim.x * blockDim.x;
    const int tid = blockIdx.x * blockDim.x + threadIdx.x;

    auto pack2 = [](float a, float b) {
        __half2 h = __floats2half2_rn(a, b);
        return *(uint32_t*)&h;
    };
    const int nx = T_TOK * D_IN / 8;
    for (int i = tid; i < nx; i += stride) {
        float4 v0 = x4[2 * i], v1 = x4[2 * i + 1];
        xo[i] = make_uint4(pack2(v0.x, v0.y), pack2(v0.z, v0.w),
                           pack2(v1.x, v1.y), pack2(v1.z, v1.w));
    }
    const int ng = TWO_DM * D_IN / 8;
    for (int i = tid; i < ng; i += stride) {
        float4 v0 = gu4[2 * i], v1 = gu4[2 * i + 1];
        go[i] = make_uint4(pack2(v0.x, v0.y), pack2(v0.z, v0.w),
                           pack2(v1.x, v1.y), pack2(v1.z, v1.w));
    }
    const int nd = D_IN * D_MOE / 8;
    for (int i = tid; i < nd; i += stride) {
        float4 v0 = dw4[2 * i], v1 = dw4[2 * i + 1];
        do_[i] = make_uint4(pack2(v0.x, v0.y), pack2(v0.z, v0.w),
                            pack2(v1.x, v1.y), pack2(v1.z, v1.w));
    }
}

// ---------------------------------------------------------------------------
// Persistent fused kernel. 512 threads = 16 warps (4 wm x 4 wn), 1 CTA/SM.
// Tile: A 256 x BK, B 128 rows x BK, 3-stage cp.async ring, SW128 swizzle.
// B smem row space (128 rows = 8 groups of 16):
//   G1: group 2j = gate h-cols [16j,16j+16), group 2j+1 = up same cols
//       -> warp wn (rows wn*32..+32): p0 = gate, p1 = up, same 16 h-cols
//   G2: contiguous down_w rows (out cols bn*128 + row)
// Mainloop identical for both; only cp.async addressing + epilogue differ.
// ---------------------------------------------------------------------------
__global__ __launch_bounds__(512, 1) void moe_fused(float* __restrict__ out) {
    extern __shared__ char smem[];
    __shared__ unsigned int s_tile;
    const uint32_t sbase = smem_u32(smem);
    const int tid = threadIdx.x, wid = tid >> 5, lane = tid & 31;
    const int wm = wid & 3, wn = wid >> 2;
    const int g = lane >> 2, q = lane & 3;
    const int r7 = lane & 7;
    const int laneRowA = ((lane >> 3) & 1) * 8 + r7;
    const int kselA = lane >> 4;
    const int laneRowB = (lane >> 4) * 8 + r7;
    const int kselB = (lane >> 3) & 1;

    for (;;) {
        __syncthreads();                       // protects s_tile + smem reuse
        if (tid == 0) s_tile = atomicAdd(&g_tile_ctr, 1u);
        __syncthreads();
        const unsigned idx = s_tile;
        if (idx >= N_TILES) break;

        const bool is_g1 = idx < G1_TILES;
        int bm, bn, kdim, nchunk;
        const __half *Ap, *Bg, *Bu, *Bd;
        if (is_g1) {
            bm = idx / 12; bn = idx % 12;
            kdim = D_IN; nchunk = D_IN / BK;
            Ap = g_xh + (size_t)bm * BM * D_IN;
            Bg = g_guw + (size_t)(bn * 64) * D_IN;           // gate rows
            Bu = g_guw + (size_t)(D_MOE + bn * 64) * D_IN;   // up rows
            Bd = nullptr;
        } else {
            const unsigned i2 = idx - G1_TILES;
            bm = i2 / 16; bn = i2 % 16;
            kdim = D_MOE; nchunk = D_MOE / BK;
            Ap = g_h + (size_t)bm * BM * D_MOE;
            Bd = g_dw + (size_t)(bn * 128) * D_MOE;
            Bg = Bu = nullptr;
            if (tid == 0) {
                while (atomicAdd(&g_ready[bm], 0u) < 12u) __nanosleep(128);
            }
            __syncthreads();
            __threadfence();                   // acquire h stores
        }

        // stage loader: A 2048 granules (4/thr), B 1024 (2/thr), 16B each
        auto load_stage = [&](int stage, int chunk) {
            const uint32_t sA = sbase + stage * STAGE_BYTES;
            const uint32_t sB = sA + A_BYTES;
            const int k0 = chunk * BK;
#pragma unroll
            for (int i = 0; i < 4; i++) {
                int gi = tid + i * 512;
                int r = gi >> 3, c = gi & 7;
                cp16(sA + r * 128 + ((c ^ (r & 7)) << 4),
                     Ap + (size_t)r * kdim + k0 + c * 8);
            }
#pragma unroll
            for (int i = 0; i < 2; i++) {
                int gi = tid + i * 512;
                int r = gi >> 3, c = gi & 7;
                const __half* src;
                if (is_g1) {
                    int grp = r >> 4, w = r & 15;
                    src = ((grp & 1) ? Bu : Bg) + (size_t)((grp >> 1) * 16 + w) * kdim;
                } else {
                    src = Bd + (size_t)r * kdim;
                }
                cp16(sB + r * 128 + ((c ^ (r & 7)) << 4), src + k0 + c * 8);
            }
            CP_COMMIT();
        };

        float acc[4][4][4];
#pragma unroll
        for (int a = 0; a < 4; a++)
#pragma unroll
            for (int b = 0; b < 4; b++)
#pragma unroll
                for (int c = 0; c < 4; c++) acc[a][b][c] = 0.f;

        load_stage(0, 0);
        load_stage(1, 1);

        for (int j = 0; j < nchunk; j++) {
            if (j == nchunk - 1) { CP_WAIT(0); } else { CP_WAIT(1); }
            __syncthreads();
            if (j + 2 < nchunk) {
                int ns = j + 2;
                load_stage(ns % S_STAGES, ns);
            }

            const uint32_t sA = sbase + (j % S_STAGES) * STAGE_BYTES;
            const uint32_t sB = sA + A_BYTES;

#pragma unroll
            for (int kk = 0; kk < 4; kk++) {
                uint32_t a[4][4];
#pragma unroll
                for (int mt = 0; mt < 4; mt++) {
                    int row = wm * 64 + mt * 16 + laneRowA;
                    uint32_t addr = sA + row * 128 + (((kk * 2 + kselA) ^ r7) << 4);
                    ldsm_x4(a[mt][0], a[mt][1], a[mt][2], a[mt][3], addr);
                }
                uint32_t b[4][2];
#pragma unroll
                for (int p = 0; p < 2; p++) {
                    int row = wn * 32 + p * 16 + laneRowB;
                    uint32_t addr = sB + row * 128 + (((kk * 2 + kselB) ^ r7) << 4);
                    ldsm_x4(b[2 * p][0], b[2 * p][1], b[2 * p + 1][0], b[2 * p + 1][1], addr);
                }
#pragma unroll
                for (int mt = 0; mt < 4; mt++)
#pragma unroll
                    for (int ni = 0; ni < 4; ni++)
                        mma_16816(acc[mt][ni], a[mt], b[ni]);
            }
        }

        if (is_g1) {
            // acc[mt][0..1] = gate, acc[mt][2..3] = up; h cols bn*64 + wn*16 + ni*8
#pragma unroll
            for (int mt = 0; mt < 4; mt++)
#pragma unroll
                for (int ni = 0; ni < 2; ni++) {
                    int row = bm * BM + wm * 64 + mt * 16 + g;
                    int col = bn * 64 + wn * 16 + ni * 8 + q * 2;
                    float* cg = acc[mt][ni];
                    float* cu = acc[mt][ni + 2];
                    __half2 h01 = __floats2half2_rn(silu_f(cg[0]) * cu[0], silu_f(cg[1]) * cu[1]);
                    __half2 h23 = __floats2half2_rn(silu_f(cg[2]) * cu[2], silu_f(cg[3]) * cu[3]);
                    *(__half2*)&g_h[(size_t)row * D_MOE + col] = h01;
                    *(__half2*)&g_h[(size_t)(row + 8) * D_MOE + col] = h23;
                }
            __threadfence();
            __syncthreads();
            if (tid == 0) atomicAdd(&g_ready[bm], 1u);
        } else {
#pragma unroll
            for (int mt = 0; mt < 4; mt++)
#pragma unroll
                for (int ni = 0; ni < 4; ni++) {
                    int row = bm * BM + wm * 64 + mt * 16 + g;
                    int col = bn * 128 + wn * 32 + ni * 8 + q * 2;
                    float* c = acc[mt][ni];
                    st_cs_f2(&out[(size_t)row * D_IN + col], c[0], c[1]);
                    st_cs_f2(&out[(size_t)(row + 8) * D_IN + col], c[2], c[3]);
                }
        }
    }
}

// ---------------------------------------------------------------------------
extern "C" void kernel_launch(void* const* d_in, const int* in_sizes, int n_in,
                              void* d_out, int out_size) {
    const float* x = (const float*)d_in[0];
    const float* gup = (const float*)d_in[1];
    const float* dp = (const float*)d_in[2];
    const int* eidx = (const int*)d_in[3];
    float* out = (float*)d_out;

    cudaFuncSetAttribute(moe_fused, cudaFuncAttributeMaxDynamicSharedMemorySize, SMEM_TOTAL);
    int nsm = 148;
    cudaDeviceGetAttribute(&nsm, cudaDevAttrMultiProcessorCount, 0);

    convert_kernel<<<2048, 256>>>(x, gup, dp, eidx);
    moe_fused<<<nsm, 512, SMEM_TOTAL>>>(out);
}

// round 13
// speedup vs baseline: 1.3492x; 1.3492x over previous
#include <cuda_runtime.h>
#include <cuda_fp16.h>
#include <cstdint>

#define T_TOK 4096
#define D_IN  2048
#define D_MOE 768
#define TWO_DM 1536

// ---- tiling (R7 proven config) ----
#define BM 128
#define BK 64                       // halves per K chunk = 128B swizzled row
#define A_BYTES  (BM * 128)         // 16 KB
#define B_BYTES  (128 * 128)        // 16 KB
#define STAGE_BYTES (A_BYTES + B_BYTES)
#define S_STAGES 3
#define SMEM_TOTAL (S_STAGES * STAGE_BYTES)   // 96 KB -> 2 CTAs/SM

// Scratch (device globals: allocation-free per harness rules)
__device__ __align__(16) __half g_xh[T_TOK * D_IN];
__device__ __align__(16) __half g_guw[TWO_DM * D_IN];
__device__ __align__(16) __half g_dw[D_IN * D_MOE];
__device__ __align__(16) __half g_h[T_TOK * D_MOE];
__device__ unsigned int g_ready[32];   // per 128-row block of h: finished G1 tiles (of 12)

// ---------------------------------------------------------------------------
// PTX helpers (non-'a' features only: cp.async, ldmatrix, mma.sync)
// ---------------------------------------------------------------------------
__device__ __forceinline__ uint32_t smem_u32(const void* p) {
    uint32_t a;
    asm("{ .reg .u64 t; cvta.to.shared.u64 t, %1; cvt.u32.u64 %0, t; }" : "=r"(a) : "l"(p));
    return a;
}
__device__ __forceinline__ void cp16(uint32_t saddr, const void* gaddr) {
    asm volatile("cp.async.cg.shared.global [%0], [%1], 16;" :: "r"(saddr), "l"(gaddr));
}
#define CP_COMMIT() asm volatile("cp.async.commit_group;" ::: "memory")
#define CP_WAIT(n)  asm volatile("cp.async.wait_group %0;" :: "n"(n) : "memory")

__device__ __forceinline__ void ldsm_x4(uint32_t& r0, uint32_t& r1, uint32_t& r2, uint32_t& r3,
                                        uint32_t addr) {
    asm volatile("ldmatrix.sync.aligned.m8n8.x4.shared.b16 {%0,%1,%2,%3}, [%4];"
                 : "=r"(r0), "=r"(r1), "=r"(r2), "=r"(r3) : "r"(addr));
}
__device__ __forceinline__ void mma_16816(float* c, const uint32_t* a, const uint32_t* b) {
    asm volatile(
        "mma.sync.aligned.m16n8k16.row.col.f32.f16.f16.f32 "
        "{%0,%1,%2,%3}, {%4,%5,%6,%7}, {%8,%9}, {%0,%1,%2,%3};"
        : "+f"(c[0]), "+f"(c[1]), "+f"(c[2]), "+f"(c[3])
        : "r"(a[0]), "r"(a[1]), "r"(a[2]), "r"(a[3]), "r"(b[0]), "r"(b[1]));
}
__device__ __forceinline__ void st_cs_f2(float* p, float a, float b) {
    asm volatile("st.global.cs.v2.f32 [%0], {%1, %2};" :: "l"(p), "f"(a), "f"(b) : "memory");
}
__device__ __forceinline__ float silu_f(float v) { return v / (1.0f + __expf(-v)); }

// ---------------------------------------------------------------------------
// fp32 -> fp16 conversion + ready-flag reset. expert_idx read on device.
// ---------------------------------------------------------------------------
__global__ void convert_kernel(const float* __restrict__ x,
                               const float* __restrict__ gup,
                               const float* __restrict__ dp,
                               const int* __restrict__ eidx) {
    if (blockIdx.x == 0 && threadIdx.x < 32) g_ready[threadIdx.x] = 0;
    const int e = *eidx;
    const float4* gu4 = (const float4*)(gup + (size_t)e * TWO_DM * D_IN);
    const float4* dw4 = (const float4*)(dp + (size_t)e * D_IN * D_MOE);
    const float4* x4 = (const float4*)x;
    uint4* xo = (uint4*)g_xh;
    uint4* go = (uint4*)g_guw;
    uint4* do_ = (uint4*)g_dw;
    const int stride = gridDim.x * blockDim.x;
    const int tid = blockIdx.x * blockDim.x + threadIdx.x;

    auto pack2 = [](float a, float b) {
        __half2 h = __floats2half2_rn(a, b);
        return *(uint32_t*)&h;
    };
    const int nx = T_TOK * D_IN / 8;
    for (int i = tid; i < nx; i += stride) {
        float4 v0 = x4[2 * i], v1 = x4[2 * i + 1];
        xo[i] = make_uint4(pack2(v0.x, v0.y), pack2(v0.z, v0.w),
                           pack2(v1.x, v1.y), pack2(v1.z, v1.w));
    }
    const int ng = TWO_DM * D_IN / 8;
    for (int i = tid; i < ng; i += stride) {
        float4 v0 = gu4[2 * i], v1 = gu4[2 * i + 1];
        go[i] = make_uint4(pack2(v0.x, v0.y), pack2(v0.z, v0.w),
                           pack2(v1.x, v1.y), pack2(v1.z, v1.w));
    }
    const int nd = D_IN * D_MOE / 8;
    for (int i = tid; i < nd; i += stride) {
        float4 v0 = dw4[2 * i], v1 = dw4[2 * i + 1];
        do_[i] = make_uint4(pack2(v0.x, v0.y), pack2(v0.z, v0.w),
                            pack2(v1.x, v1.y), pack2(v1.z, v1.w));
    }
}

// ---------------------------------------------------------------------------
// Pipelined HMMA GEMM, 2 CTAs/SM, 256 threads = 8 warps (4M x 2N). R7 config.
// G1 (IS_G1): B = 64 gate + 64 up rows, epilogue SwiGLU -> g_h, then publishes
//             g_ready[bm]. G2: spins on g_ready[bm]==12 BEFORE first load,
//             B = 128 down_w rows, epilogue fp32 streaming stores -> out.
// Launched back-to-back in one stream: G2 CTAs overlap G1's ragged tail.
// ---------------------------------------------------------------------------
template <int KDIM, int NCHUNK, bool IS_G1>
__global__ __launch_bounds__(256, 2) void gemm_hmma(float* __restrict__ out) {
    extern __shared__ char smem[];
    const uint32_t sbase = smem_u32(smem);
    const int tid = threadIdx.x, wid = tid >> 5, lane = tid & 31;
    const int wm = wid & 3, wn = wid >> 2;
    const int g = lane >> 2, q = lane & 3;
    const int bn = blockIdx.x, bm = blockIdx.y;

    if (!IS_G1) {
        // wait until this 128-row block of h is fully produced by G1
        if (tid == 0) {
            while (atomicAdd(&g_ready[bm], 0u) < 12u) __nanosleep(64);
        }
        __syncthreads();
        __threadfence();   // acquire ordering for g_h reads below
    }

    const __half *Ap, *Bg, *Bu, *Bp;
    if (IS_G1) {
        Ap = g_xh + (size_t)bm * BM * KDIM;
        Bg = g_guw + (size_t)(bn * 64) * KDIM;
        Bu = g_guw + (size_t)(D_MOE + bn * 64) * KDIM;
        Bp = nullptr;
    } else {
        Ap = g_h + (size_t)bm * BM * KDIM;
        Bp = g_dw + (size_t)(bn * 128) * KDIM;
        Bg = Bu = nullptr;
    }

    auto load_stage = [&](int stage, int chunk) {
        const uint32_t sA = sbase + stage * STAGE_BYTES;
        const uint32_t sB = sA + A_BYTES;
        const int k0 = chunk * BK;
#pragma unroll
        for (int i = 0; i < 4; i++) {
            int gi = tid + i * 256;
            int r = gi >> 3, c = gi & 7;
            cp16(sA + r * 128 + ((c ^ (r & 7)) << 4), Ap + (size_t)r * KDIM + k0 + c * 8);
        }
#pragma unroll
        for (int i = 0; i < 4; i++) {
            int gi = tid + i * 256;
            int r = gi >> 3, c = gi & 7;
            const __half* src;
            if (IS_G1)
                src = (r < 64) ? (Bg + (size_t)r * KDIM) : (Bu + (size_t)(r - 64) * KDIM);
            else
                src = Bp + (size_t)r * KDIM;
            cp16(sB + r * 128 + ((c ^ (r & 7)) << 4), src + k0 + c * 8);
        }
        CP_COMMIT();
    };

    const int r7 = lane & 7;
    const int laneRowA = ((lane >> 3) & 1) * 8 + r7;
    const int kselA = lane >> 4;
    const int laneRowB = (lane >> 4) * 8 + r7;
    const int kselB = (lane >> 3) & 1;

    float acc[2][8][4];
#pragma unroll
    for (int a = 0; a < 2; a++)
#pragma unroll
        for (int b = 0; b < 8; b++)
#pragma unroll
            for (int c = 0; c < 4; c++) acc[a][b][c] = 0.f;

    load_stage(0, 0);
    load_stage(1, 1);

    for (int j = 0; j < NCHUNK; j++) {
        if (j == NCHUNK - 1) { CP_WAIT(0); } else { CP_WAIT(1); }
        __syncthreads();
        if (j + 2 < NCHUNK) load_stage((j + 2) % S_STAGES, j + 2);

        const uint32_t sA = sbase + (j % S_STAGES) * STAGE_BYTES;
        const uint32_t sB = sA + A_BYTES;

#pragma unroll
        for (int kk = 0; kk < 4; kk++) {
            uint32_t a[2][4];
#pragma unroll
            for (int mt = 0; mt < 2; mt++) {
                int row = wm * 32 + mt * 16 + laneRowA;
                uint32_t addr = sA + row * 128 + (((kk * 2 + kselA) ^ r7) << 4);
                ldsm_x4(a[mt][0], a[mt][1], a[mt][2], a[mt][3], addr);
            }
            uint32_t b[8][2];
#pragma unroll
            for (int p = 0; p < 4; p++) {
                int nbase;
                if (IS_G1) nbase = (p < 2) ? (wn * 32 + p * 16) : (64 + wn * 32 + (p - 2) * 16);
                else       nbase = wn * 64 + p * 16;
                int row = nbase + laneRowB;
                uint32_t addr = sB + row * 128 + (((kk * 2 + kselB) ^ r7) << 4);
                ldsm_x4(b[2 * p][0], b[2 * p][1], b[2 * p + 1][0], b[2 * p + 1][1], addr);
            }
#pragma unroll
            for (int mt = 0; mt < 2; mt++)
#pragma unroll
                for (int ni = 0; ni < 8; ni++)
                    mma_16816(acc[mt][ni], a[mt], b[ni]);
        }
    }

    if (IS_G1) {
#pragma unroll
        for (int mt = 0; mt < 2; mt++)
#pragma unroll
            for (int ni = 0; ni < 4; ni++) {
                int row = bm * BM + wm * 32 + mt * 16 + g;
                int col = bn * 64 + wn * 32 + ni * 8 + q * 2;
                float* cg = acc[mt][ni];
                float* cu = acc[mt][ni + 4];
                __half2 h01 = __floats2half2_rn(silu_f(cg[0]) * cu[0], silu_f(cg[1]) * cu[1]);
                __half2 h23 = __floats2half2_rn(silu_f(cg[2]) * cu[2], silu_f(cg[3]) * cu[3]);
                *(__half2*)&g_h[(size_t)row * D_MOE + col] = h01;
                *(__half2*)&g_h[(size_t)(row + 8) * D_MOE + col] = h23;
            }
        // publish: this (bm, bn) h-tile is complete
        __threadfence();
        __syncthreads();
        if (tid == 0) atomicAdd(&g_ready[bm], 1u);
    } else {
#pragma unroll
        for (int mt = 0; mt < 2; mt++)
#pragma unroll
            for (int ni = 0; ni < 8; ni++) {
                int row = bm * BM + wm * 32 + mt * 16 + g;
                int col = bn * 128 + wn * 64 + ni * 8 + q * 2;
                float* c = acc[mt][ni];
                st_cs_f2(&out[(size_t)row * D_IN + col], c[0], c[1]);
                st_cs_f2(&out[(size_t)(row + 8) * D_IN + col], c[2], c[3]);
            }
    }
}

// ---------------------------------------------------------------------------
extern "C" void kernel_launch(void* const* d_in, const int* in_sizes, int n_in,
                              void* d_out, int out_size) {
    const float* x = (const float*)d_in[0];
    const float* gup = (const float*)d_in[1];
    const float* dp = (const float*)d_in[2];
    const int* eidx = (const int*)d_in[3];
    float* out = (float*)d_out;

    cudaFuncSetAttribute(gemm_hmma<D_IN, D_IN / BK, true>,
                         cudaFuncAttributeMaxDynamicSharedMemorySize, SMEM_TOTAL);
    cudaFuncSetAttribute(gemm_hmma<D_MOE, D_MOE / BK, false>,
                         cudaFuncAttributeMaxDynamicSharedMemorySize, SMEM_TOTAL);

    convert_kernel<<<2048, 256>>>(x, gup, dp, eidx);
    // G1: grid (bn=12, bm=32) bm-major completion; G2 launched immediately,
    // its CTAs gate themselves on g_ready[bm] and fill G1's tail.
    gemm_hmma<D_IN, D_IN / BK, true><<<dim3(12, 32), 256, SMEM_TOTAL>>>(nullptr);
    gemm_hmma<D_MOE, D_MOE / BK, false><<<dim3(16, 32), 256, SMEM_TOTAL>>>(out);
}